// round 2
// baseline (speedup 1.0000x reference)
#include <cuda_runtime.h>

// Problem constants
#define B_  2
#define E_  16
#define H_  160
#define W_  288
#define N_  12
#define T_  2
#define HW_ (H_ * W_)           // 46080
#define P_  (T_ * HW_)          // 92160 pixels per instance
#define BN_ (B_ * N_)           // 24 instances
#define NBINS 131072            // error bins over [0, 2]
#define BIN_SCALE 65536.0f      // NBINS / 2
#define CHUNK 2048
#define NCHUNK (NBINS / CHUNK)  // 64

// Scratch (static __device__ arrays — no allocation allowed)
__device__ unsigned int d_histP[BN_ * NBINS];   // 12.6 MB
__device__ unsigned int d_histN[BN_ * NBINS];   // 12.6 MB
__device__ double       d_S1[BN_ * E_];
__device__ double       d_S2[BN_ * E_];
__device__ unsigned int d_cnt[BN_];
__device__ float        d_mean[BN_ * E_];
__device__ float        d_var [BN_ * E_];
__device__ unsigned int d_chP[BN_ * NCHUNK];
__device__ unsigned int d_chN[BN_ * NCHUNK];
__device__ double       d_total;

// ---------------------------------------------------------------------------
// Kernel 0: clear all accumulators / histograms
// ---------------------------------------------------------------------------
__global__ void k_clear() {
    size_t i = (size_t)blockIdx.x * blockDim.x + threadIdx.x;
    size_t stride = (size_t)gridDim.x * blockDim.x;
    const size_t n4 = (size_t)BN_ * NBINS / 4;
    uint4 z = make_uint4(0u, 0u, 0u, 0u);
    uint4* hp = reinterpret_cast<uint4*>(d_histP);
    uint4* hn = reinterpret_cast<uint4*>(d_histN);
    for (size_t j = i; j < n4; j += stride) { hp[j] = z; hn[j] = z; }
    if (i < BN_ * E_) { d_S1[i] = 0.0; d_S2[i] = 0.0; }
    if (i < BN_)      { d_cnt[i] = 0u; }
    if (i == 0)       { d_total = 0.0; }
}

// ---------------------------------------------------------------------------
// Kernel 1: masked sums  S1 = sum(m*x), S2 = sum(m*x^2), cnt = sum(m)
// grid (64 chunks, B_), block 512 (16 warps; warp w handles embed dim e = w)
// Each chunk of 1440 pixels lies entirely inside one frame t.
// ---------------------------------------------------------------------------
__global__ void k_stats(const float* __restrict__ mf1,
                        const float* __restrict__ mf2,
                        const int*   __restrict__ gt) {
    const int b    = blockIdx.y;
    const int e    = threadIdx.x >> 5;
    const int lane = threadIdx.x & 31;
    const int CPIX = P_ / 64;               // 1440
    const int p0   = blockIdx.x * CPIX;
    const int t    = p0 / HW_;
    const int hw0  = p0 - t * HW_;

    const float* f = (t == 0 ? mf1 : mf2) + ((size_t)b * E_ + e) * HW_ + hw0;
    const int*   g = gt + (((size_t)b * N_) * T_ + t) * HW_ + hw0;  // n stride = T_*HW_

    float s1[N_], s2[N_];
    int   c[N_];
#pragma unroll
    for (int n = 0; n < N_; n++) { s1[n] = 0.f; s2[n] = 0.f; c[n] = 0; }

    for (int k = lane; k < CPIX; k += 32) {
        float x  = f[k];
        float x2 = x * x;
#pragma unroll
        for (int n = 0; n < N_; n++) {
            int   mv = g[(size_t)n * (T_ * HW_) + k];   // 0 or 1
            float fm = (float)mv;
            s1[n] = fmaf(fm, x,  s1[n]);
            s2[n] = fmaf(fm, x2, s2[n]);
            c[n] += mv;
        }
    }

#pragma unroll
    for (int n = 0; n < N_; n++) {
        float a  = s1[n];
        float bb = s2[n];
        for (int off = 16; off; off >>= 1) {
            a  += __shfl_down_sync(0xffffffffu, a,  off);
            bb += __shfl_down_sync(0xffffffffu, bb, off);
        }
        if (lane == 0) {
            atomicAdd(&d_S1[((size_t)b * N_ + n) * E_ + e], (double)a);
            atomicAdd(&d_S2[((size_t)b * N_ + n) * E_ + e], (double)bb);
        }
    }
    if (e == 0) {
#pragma unroll
        for (int n = 0; n < N_; n++) {
            int cc = c[n];
            for (int off = 16; off; off >>= 1)
                cc += __shfl_down_sync(0xffffffffu, cc, off);
            if (lane == 0) atomicAdd(&d_cnt[b * N_ + n], (unsigned)cc);
        }
    }
}

// ---------------------------------------------------------------------------
// Kernel 1b: finalize mean / unbiased var
// ---------------------------------------------------------------------------
__global__ void k_finalize() {
    int i = threadIdx.x;                 // 0 .. BN_*E_-1 (384)
    if (i >= BN_ * E_) return;
    int inst = i / E_;
    double cnt  = (double)d_cnt[inst];
    double s1   = d_S1[i];
    double s2   = d_S2[i];
    double mean = s1 / cnt;
    double var  = (s2 - s1 * s1 / cnt) / (cnt - 1.0);
    d_mean[i] = (float)mean;
    d_var[i]  = (float)var;
}

// ---------------------------------------------------------------------------
// Kernel 2: per-pixel Mahalanobis-ish distance -> error -> histogram
// grid (P_/256, B_), block 256. One thread = one pixel (t,hw) of one batch.
// ---------------------------------------------------------------------------
__global__ void k_hist(const float* __restrict__ mf1,
                       const float* __restrict__ mf2,
                       const int*   __restrict__ gt) {
    __shared__ float sm_mean[N_ * E_];
    __shared__ float sm_var [N_ * E_];
    const int b   = blockIdx.y;
    const int tid = threadIdx.x;
    if (tid < N_ * E_) {
        sm_mean[tid] = d_mean[b * N_ * E_ + tid];
        sm_var [tid] = d_var [b * N_ * E_ + tid];
    }
    __syncthreads();

    const int p  = blockIdx.x * 256 + tid;     // < P_ exactly
    const int t  = p / HW_;
    const int hw = p - t * HW_;

    const float* f = (t == 0 ? mf1 : mf2) + (size_t)b * E_ * HW_ + hw;
    float x[E_];
#pragma unroll
    for (int e = 0; e < E_; e++) x[e] = f[(size_t)e * HW_];

#pragma unroll
    for (int n = 0; n < N_; n++) {
        int mv = gt[(((size_t)b * N_ + n) * T_ + t) * HW_ + hw];
        float d = 0.f;
#pragma unroll
        for (int e = 0; e < E_; e++) {
            float diff = x[e] - sm_mean[n * E_ + e];
            d = fmaf(diff * diff, sm_var[n * E_ + e], d);
        }
        float q   = expf(-0.5f * d);            // in (0, 1]
        float err = mv ? (2.0f - 2.0f * q) : (2.0f * q);   // = relu(error), always >= 0
        int bin   = (int)(err * BIN_SCALE);
        bin       = bin < (NBINS - 1) ? bin : (NBINS - 1);
        unsigned int* h = mv ? d_histP : d_histN;
        atomicAdd(&h[(size_t)(b * N_ + n) * NBINS + bin], 1u);
    }
}

// ---------------------------------------------------------------------------
// Kernel 3a: per (instance, chunk) histogram sums
// ---------------------------------------------------------------------------
__global__ void k_chunk_sums() {
    const int inst = blockIdx.y;
    const int c    = blockIdx.x;
    const int tid  = threadIdx.x;       // 256
    const size_t base = (size_t)inst * NBINS + (size_t)c * CHUNK;
    unsigned sp_ = 0, sn_ = 0;
    for (int j = tid; j < CHUNK; j += 256) {
        sp_ += d_histP[base + j];
        sn_ += d_histN[base + j];
    }
    __shared__ unsigned sp[256], sn[256];
    sp[tid] = sp_; sn[tid] = sn_;
    __syncthreads();
    for (int s = 128; s; s >>= 1) {
        if (tid < s) { sp[tid] += sp[tid + s]; sn[tid] += sn[tid + s]; }
        __syncthreads();
    }
    if (tid == 0) {
        d_chP[inst * NCHUNK + c] = sp[0];
        d_chN[inst * NCHUNK + c] = sn[0];
    }
}

// ---------------------------------------------------------------------------
// Kernel 3b: exclusive scan of chunk sums (ascending bin order), in place
// ---------------------------------------------------------------------------
__global__ void k_chunk_scan() {
    const int inst = blockIdx.x;
    unsigned ap = 0, an = 0;
    for (int c = 0; c < NCHUNK; c++) {
        unsigned tp = d_chP[inst * NCHUNK + c];
        unsigned tn = d_chN[inst * NCHUNK + c];
        d_chP[inst * NCHUNK + c] = ap;
        d_chN[inst * NCHUNK + c] = an;
        ap += tp; an += tn;
    }
}

// ---------------------------------------------------------------------------
// Kernel 3c: per-chunk bin scan + Lovasz contribution.
// Sorted order is DESCENDING error.  With ascending exclusive prefixes
// (exclP/exclN) the consumed-before/after counts for bin b are:
//   before: cp0 = totPos - (exclP + cntP),  cn0 = totNeg - (exclN + cntN)
//   after : cp1 = totPos - exclP,           cn1 = totNeg - exclN
//   J(cp,cn) = 1 - (gts - cp)/(gts + cn);   contrib = e_rep * (J1 - J0)
// ---------------------------------------------------------------------------
__global__ void k_loss() {
    const int inst = blockIdx.y;
    const int c    = blockIdx.x;
    const int tid  = threadIdx.x;      // 256 threads * 8 bins = 2048 = CHUNK
    const size_t base = (size_t)inst * NBINS + (size_t)c * CHUNK;

    unsigned cntP[8], cntN[8];
    unsigned tp = 0, tn = 0;
#pragma unroll
    for (int j = 0; j < 8; j++) {
        cntP[j] = d_histP[base + tid * 8 + j];
        cntN[j] = d_histN[base + tid * 8 + j];
        tp += cntP[j]; tn += cntN[j];
    }

    __shared__ unsigned sp[256], sn[256];
    sp[tid] = tp; sn[tid] = tn;
    __syncthreads();
    for (int s = 1; s < 256; s <<= 1) {
        unsigned vp = (tid >= s) ? sp[tid - s] : 0u;
        unsigned vn = (tid >= s) ? sn[tid - s] : 0u;
        __syncthreads();
        sp[tid] += vp; sn[tid] += vn;
        __syncthreads();
    }
    unsigned runP = sp[tid] - tp + d_chP[inst * NCHUNK + c];  // exclusive ascending prefix
    unsigned runN = sn[tid] - tn + d_chN[inst * NCHUNK + c];

    const double totPos = (double)d_cnt[inst];
    const double totNeg = (double)P_ - totPos;
    const double gts    = totPos;
    const double dbin   = 2.0 / (double)NBINS;

    double acc = 0.0;
#pragma unroll
    for (int j = 0; j < 8; j++) {
        unsigned cp = cntP[j], cn = cntN[j];
        if (cp | cn) {
            double cp0 = totPos - (double)(runP + cp);
            double cn0 = totNeg - (double)(runN + cn);
            double cp1 = totPos - (double)runP;
            double cn1 = totNeg - (double)runN;
            double J0 = 1.0 - (gts - cp0) / (gts + cn0);
            double J1 = 1.0 - (gts - cp1) / (gts + cn1);
            double e_rep = ((double)(c * CHUNK + tid * 8 + j) + 0.5) * dbin;
            acc += e_rep * (J1 - J0);
        }
        runP += cp; runN += cn;
    }

    __shared__ double sd[256];
    sd[tid] = acc;
    __syncthreads();
    for (int s = 128; s; s >>= 1) {
        if (tid < s) sd[tid] += sd[tid + s];
        __syncthreads();
    }
    if (tid == 0) atomicAdd(&d_total, sd[0]);
}

// ---------------------------------------------------------------------------
// Kernel 4: write scalar output (mean over B*N instances)
// ---------------------------------------------------------------------------
__global__ void k_out(float* out) {
    out[0] = (float)(d_total / (double)BN_);
}

extern "C" void kernel_launch(void* const* d_in, const int* in_sizes, int n_in,
                              void* d_out, int out_size) {
    const float* mf1 = (const float*)d_in[0];
    const float* mf2 = (const float*)d_in[1];
    const int*   gt  = (const int*)d_in[2];

    k_clear<<<2048, 256>>>();
    k_stats<<<dim3(64, B_), 512>>>(mf1, mf2, gt);
    k_finalize<<<1, 384>>>();
    k_hist<<<dim3(P_ / 256, B_), 256>>>(mf1, mf2, gt);
    k_chunk_sums<<<dim3(NCHUNK, BN_), 256>>>();
    k_chunk_scan<<<BN_, 1>>>();
    k_loss<<<dim3(NCHUNK, BN_), 256>>>();
    k_out<<<1, 1>>>((float*)d_out);
}

// round 3
// speedup vs baseline: 1.5597x; 1.5597x over previous
#include <cuda_runtime.h>

// Problem constants
#define B_  2
#define E_  16
#define H_  160
#define W_  288
#define N_  12
#define T_  2
#define HW_ (H_ * W_)           // 46080
#define P_  (T_ * HW_)          // 92160 pixels per instance
#define BN_ (B_ * N_)           // 24 instances
#define NE_ (N_ * E_)           // 192
#define NBINS 65536             // error bins over [0, 2]
#define BIN_SCALE 32768.0f      // NBINS / 2
#define CHUNK 1024
#define NCHUNK (NBINS / CHUNK)  // 64
#define NSLOT (BN_ * 2)         // slot = inst*2 + mv

// Scratch (static __device__ arrays — no allocation allowed)
__device__ unsigned int d_hist[NSLOT * NBINS];      // 12.6 MB
__device__ unsigned int d_pack[B_ * P_];            // packed masks, 737 KB
__device__ double       d_S1[BN_ * E_];
__device__ double       d_S2[BN_ * E_];
__device__ unsigned int d_cnt[BN_];
__device__ float        d_mean[BN_ * E_];
__device__ float        d_nhv [BN_ * E_];           // -0.5 * var
__device__ unsigned int d_chP[BN_ * NCHUNK];
__device__ unsigned int d_chN[BN_ * NCHUNK];
__device__ double       d_total;
__device__ unsigned int d_tick1;
__device__ unsigned int d_tick2;

// ---------------------------------------------------------------------------
// Kernel 0: clear histogram + accumulators
// ---------------------------------------------------------------------------
__global__ void k_clear() {
    size_t i = (size_t)blockIdx.x * blockDim.x + threadIdx.x;
    size_t stride = (size_t)gridDim.x * blockDim.x;
    const size_t n4 = (size_t)NSLOT * NBINS / 4;
    uint4 z = make_uint4(0u, 0u, 0u, 0u);
    uint4* h = reinterpret_cast<uint4*>(d_hist);
    for (size_t j = i; j < n4; j += stride) h[j] = z;
    if (i < BN_ * E_) { d_S1[i] = 0.0; d_S2[i] = 0.0; }
    if (i < BN_)      { d_cnt[i] = 0u; }
    if (i == 0)       { d_total = 0.0; d_tick1 = 0u; d_tick2 = 0u; }
}

// ---------------------------------------------------------------------------
// Kernel 1: pack masks + masked sums + (fused) finalize of mean/var.
// grid (64 chunks, B_), block 512.  Chunk of 1440 pixels lies in one frame t.
// Phase 1: pack 12 masks/pixel into one uint32 (shared + global).
// Phase 2: warp w = embed dim e accumulates S1, S2 (bit-predicated adds).
// ---------------------------------------------------------------------------
__global__ void __launch_bounds__(512) k_stats(const float* __restrict__ mf1,
                                               const float* __restrict__ mf2,
                                               const int*   __restrict__ gt) {
    __shared__ unsigned int spack[P_ / 64];   // 1440
    const int b    = blockIdx.y;
    const int tid  = threadIdx.x;
    const int CPIX = P_ / 64;                 // 1440
    const int p0   = blockIdx.x * CPIX;
    const int t    = p0 / HW_;
    const int hw0  = p0 - t * HW_;

    // Phase 1: pack
    const int* g0 = gt + (((size_t)b * N_) * T_ + t) * HW_ + hw0;
    for (int k = tid; k < CPIX; k += 512) {
        unsigned w = 0u;
#pragma unroll
        for (int n = 0; n < N_; n++)
            w |= ((unsigned)g0[(size_t)n * (T_ * HW_) + k]) << n;
        spack[k] = w;
        d_pack[(size_t)b * P_ + p0 + k] = w;
    }
    __syncthreads();

    // Phase 2: accumulate
    const int e    = tid >> 5;
    const int lane = tid & 31;
    const float* f = (t == 0 ? mf1 : mf2) + ((size_t)b * E_ + e) * HW_ + hw0;

    float s1[N_], s2[N_];
    int   c[N_];
#pragma unroll
    for (int n = 0; n < N_; n++) { s1[n] = 0.f; s2[n] = 0.f; c[n] = 0; }

    for (int k = lane; k < CPIX; k += 32) {
        float x  = f[k];
        float x2 = x * x;
        unsigned pw = spack[k];
#pragma unroll
        for (int n = 0; n < N_; n++) {
            if ((pw >> n) & 1u) { s1[n] += x; s2[n] += x2; c[n]++; }
        }
    }

#pragma unroll
    for (int n = 0; n < N_; n++) {
        float a  = s1[n];
        float bb = s2[n];
        for (int off = 16; off; off >>= 1) {
            a  += __shfl_down_sync(0xffffffffu, a,  off);
            bb += __shfl_down_sync(0xffffffffu, bb, off);
        }
        if (lane == 0) {
            atomicAdd(&d_S1[((size_t)b * N_ + n) * E_ + e], (double)a);
            atomicAdd(&d_S2[((size_t)b * N_ + n) * E_ + e], (double)bb);
        }
    }
    if (e == 0) {
#pragma unroll
        for (int n = 0; n < N_; n++) {
            int cc = c[n];
            for (int off = 16; off; off >>= 1)
                cc += __shfl_down_sync(0xffffffffu, cc, off);
            if (lane == 0) atomicAdd(&d_cnt[b * N_ + n], (unsigned)cc);
        }
    }

    // Fused finalize (last block)
    __threadfence();
    __shared__ bool isLast;
    if (tid == 0) isLast = (atomicAdd(&d_tick1, 1u) == (unsigned)(64 * B_ - 1));
    __syncthreads();
    if (isLast && tid < BN_ * E_) {
        int inst   = tid / E_;
        double cnt = (double)d_cnt[inst];
        double s1v = d_S1[tid];
        double s2v = d_S2[tid];
        double mean = s1v / cnt;
        double var  = (s2v - s1v * s1v / cnt) / (cnt - 1.0);
        d_mean[tid] = (float)mean;
        d_nhv[tid]  = (float)(-0.5 * var);
    }
}

// ---------------------------------------------------------------------------
// Kernel 2: per-pixel distance -> error -> histogram
// grid 1440, block 128. One thread = one pixel (covers both batches).
// ---------------------------------------------------------------------------
__global__ void __launch_bounds__(128) k_hist(const float* __restrict__ mf1,
                                              const float* __restrict__ mf2) {
    __shared__ float sm_mean[NE_];
    __shared__ float sm_nhv [NE_];
    const int tid = threadIdx.x;
    const int b   = (blockIdx.x * 128) / P_;         // uniform in block
    for (int i = tid; i < NE_; i += 128) {
        sm_mean[i] = d_mean[b * NE_ + i];
        sm_nhv [i] = d_nhv [b * NE_ + i];
    }
    __syncthreads();

    const int pp = blockIdx.x * 128 + tid;           // < B_*P_
    const int p  = pp - b * P_;
    const int t  = p / HW_;
    const int hw = p - t * HW_;

    const float* f = (t == 0 ? mf1 : mf2) + (size_t)b * E_ * HW_ + hw;
    float x[E_];
#pragma unroll
    for (int e = 0; e < E_; e++) x[e] = f[(size_t)e * HW_];

    const unsigned pw = d_pack[pp];

#pragma unroll
    for (int n = 0; n < N_; n++) {
        float d = 0.f;
#pragma unroll
        for (int e = 0; e < E_; e++) {
            float diff = x[e] - sm_mean[n * E_ + e];
            d = fmaf(diff * diff, sm_nhv[n * E_ + e], d);  // d = -0.5 * sum
        }
        float q   = __expf(d);                       // in (0, 1]
        unsigned mv = (pw >> n) & 1u;
        float err = mv ? (2.0f - 2.0f * q) : (2.0f * q);
        int bin   = (int)(err * BIN_SCALE);
        bin       = bin < (NBINS - 1) ? bin : (NBINS - 1);
        int slot  = ((b * N_ + n) << 1) | (int)mv;
        atomicAdd(&d_hist[(size_t)slot * NBINS + bin], 1u);
    }
}

// ---------------------------------------------------------------------------
// Kernel 3: per (instance, chunk) histogram sums (both slots)
// ---------------------------------------------------------------------------
__global__ void __launch_bounds__(256) k_chunk_sums() {
    const int inst = blockIdx.y;
    const int c    = blockIdx.x;
    const int tid  = threadIdx.x;                    // 256; 4 bins each
    const size_t baseN = ((size_t)(inst * 2)     * NBINS) + (size_t)c * CHUNK;
    const size_t baseP = ((size_t)(inst * 2 + 1) * NBINS) + (size_t)c * CHUNK;
    uint4 vp = *reinterpret_cast<const uint4*>(&d_hist[baseP + tid * 4]);
    uint4 vn = *reinterpret_cast<const uint4*>(&d_hist[baseN + tid * 4]);
    unsigned sp_ = vp.x + vp.y + vp.z + vp.w;
    unsigned sn_ = vn.x + vn.y + vn.z + vn.w;
    __shared__ unsigned sp[256], sn[256];
    sp[tid] = sp_; sn[tid] = sn_;
    __syncthreads();
    for (int s = 128; s; s >>= 1) {
        if (tid < s) { sp[tid] += sp[tid + s]; sn[tid] += sn[tid + s]; }
        __syncthreads();
    }
    if (tid == 0) {
        d_chP[inst * NCHUNK + c] = sp[0];
        d_chN[inst * NCHUNK + c] = sn[0];
    }
}

// ---------------------------------------------------------------------------
// Kernel 4: per-chunk bin scan + Lovasz contribution + (fused) scalar output.
// Each block computes its own chunk-prefix from the 64 raw chunk sums.
// Sorted order is DESCENDING error; ascending exclusive prefixes give:
//   before: cp0 = totPos - (excl + cnt), after: cp1 = totPos - excl
//   J(cp,cn) = 1 - (gts - cp)/(gts + cn);  contrib = e_rep * (J1 - J0)
// ---------------------------------------------------------------------------
__global__ void __launch_bounds__(256) k_loss(float* __restrict__ out) {
    const int inst = blockIdx.y;
    const int c    = blockIdx.x;
    const int tid  = threadIdx.x;                    // 256 threads * 4 bins
    const size_t baseN = ((size_t)(inst * 2)     * NBINS) + (size_t)c * CHUNK;
    const size_t baseP = ((size_t)(inst * 2 + 1) * NBINS) + (size_t)c * CHUNK;

    // chunk-prefix (sum of chunk sums below c)
    __shared__ unsigned rp[64], rn[64];
    if (tid < 64) {
        rp[tid] = (tid < c) ? d_chP[inst * NCHUNK + tid] : 0u;
        rn[tid] = (tid < c) ? d_chN[inst * NCHUNK + tid] : 0u;
    }
    __syncthreads();
    for (int s = 32; s; s >>= 1) {
        if (tid < s) { rp[tid] += rp[tid + s]; rn[tid] += rn[tid + s]; }
        __syncthreads();
    }

    uint4 vp = *reinterpret_cast<const uint4*>(&d_hist[baseP + tid * 4]);
    uint4 vn = *reinterpret_cast<const uint4*>(&d_hist[baseN + tid * 4]);
    unsigned cntP[4] = {vp.x, vp.y, vp.z, vp.w};
    unsigned cntN[4] = {vn.x, vn.y, vn.z, vn.w};
    unsigned tp = cntP[0] + cntP[1] + cntP[2] + cntP[3];
    unsigned tn = cntN[0] + cntN[1] + cntN[2] + cntN[3];

    __shared__ unsigned sp[256], sn[256];
    sp[tid] = tp; sn[tid] = tn;
    __syncthreads();
    for (int s = 1; s < 256; s <<= 1) {
        unsigned vpv = (tid >= s) ? sp[tid - s] : 0u;
        unsigned vnv = (tid >= s) ? sn[tid - s] : 0u;
        __syncthreads();
        sp[tid] += vpv; sn[tid] += vnv;
        __syncthreads();
    }
    unsigned runP = sp[tid] - tp + rp[0];            // exclusive ascending prefix
    unsigned runN = sn[tid] - tn + rn[0];

    const double totPos = (double)d_cnt[inst];
    const double totNeg = (double)P_ - totPos;
    const double gts    = totPos;
    const double dbin   = 2.0 / (double)NBINS;

    double acc = 0.0;
#pragma unroll
    for (int j = 0; j < 4; j++) {
        unsigned cp = cntP[j], cn = cntN[j];
        if (cp | cn) {
            double cp0 = totPos - (double)(runP + cp);
            double cn0 = totNeg - (double)(runN + cn);
            double cp1 = totPos - (double)runP;
            double cn1 = totNeg - (double)runN;
            double J0 = 1.0 - (gts - cp0) / (gts + cn0);
            double J1 = 1.0 - (gts - cp1) / (gts + cn1);
            double e_rep = ((double)(c * CHUNK + tid * 4 + j) + 0.5) * dbin;
            acc += e_rep * (J1 - J0);
        }
        runP += cp; runN += cn;
    }

    __shared__ double sd[256];
    sd[tid] = acc;
    __syncthreads();
    for (int s = 128; s; s >>= 1) {
        if (tid < s) sd[tid] += sd[tid + s];
        __syncthreads();
    }
    if (tid == 0) atomicAdd(&d_total, sd[0]);

    // Fused scalar output (last block)
    __threadfence();
    __shared__ bool isLast;
    if (tid == 0) isLast = (atomicAdd(&d_tick2, 1u) == (unsigned)(NCHUNK * BN_ - 1));
    __syncthreads();
    if (isLast && tid == 0) out[0] = (float)(d_total / (double)BN_);
}

extern "C" void kernel_launch(void* const* d_in, const int* in_sizes, int n_in,
                              void* d_out, int out_size) {
    const float* mf1 = (const float*)d_in[0];
    const float* mf2 = (const float*)d_in[1];
    const int*   gt  = (const int*)d_in[2];

    k_clear<<<1184, 256>>>();
    k_stats<<<dim3(64, B_), 512>>>(mf1, mf2, gt);
    k_hist<<<(B_ * P_) / 128, 128>>>(mf1, mf2);
    k_chunk_sums<<<dim3(NCHUNK, BN_), 256>>>();
    k_loss<<<dim3(NCHUNK, BN_), 256>>>((float*)d_out);
}